// round 3
// baseline (speedup 1.0000x reference)
#include <cuda_runtime.h>

#define S_LEN 2048
#define BATCH 128
#define IN_DIM 64
#define HID 128
#define G4 512
#define OUT_DIM 64
#define NCTA 128

// ---- static device scratch (no allocation allowed) ----
__device__ float g_Xp[(size_t)S_LEN * G4 * BATCH];   // [s][n][b]  512 MB
__device__ float g_hs[(size_t)S_LEN * HID * BATCH];  // [s][h][b]  128 MB
__device__ float g_h[HID * BATCH];                   // [h][b]
__device__ float g_xh[2 * HID * BATCH];              // [k2][b]  (x_in rows 0..127, h_in rows 128..255)
__device__ unsigned g_bar[2 * S_LEN];                // per-step barrier counters

#define REC_SMEM ((256 * 132 + 512 + 1024 + 512 + 4) * 4)
#define OUT_SMEM ((16384 + 128 * 65) * 4)

__global__ void init_kernel() {
    int t = blockIdx.x * blockDim.x + threadIdx.x;
    if (t < 2 * S_LEN) g_bar[t] = 0u;
    if (t < HID * BATCH) g_h[t] = 0.0f;
}

// ---- Kernel 1: Xp[s][n][b] = b_out[n] + sum_i x[b][i][s] * Wx_out[i][n] ----
__global__ __launch_bounds__(256) void xproj_kernel(const float* __restrict__ x,
                                                    const float* __restrict__ Wx,
                                                    const float* __restrict__ bo) {
    __shared__ float xs[IN_DIM * 33];  // [i][b], padded
    const int s = blockIdx.x;
    const int b0 = blockIdx.y * 32;
    const int t = threadIdx.x;
    const int b = t & 31;
    const int og = t >> 5;        // 8 groups x 64 n
    const int n0 = og * 64;

    for (int q = t; q < 32 * IN_DIM; q += 256) {
        int bb = q >> 6, i = q & 63;
        xs[i * 33 + bb] = x[((size_t)(b0 + bb) * IN_DIM + i) * S_LEN + s];
    }
    __syncthreads();

    float acc[64];
#pragma unroll
    for (int j = 0; j < 64; j++) acc[j] = 0.f;

#pragma unroll 2
    for (int k = 0; k < IN_DIM; k++) {
        float xv = xs[k * 33 + b];
        const float4* wr = (const float4*)(Wx + (size_t)k * G4 + n0);
#pragma unroll
        for (int j4 = 0; j4 < 16; j4++) {
            float4 w = __ldg(&wr[j4]);
            acc[4 * j4 + 0] = fmaf(xv, w.x, acc[4 * j4 + 0]);
            acc[4 * j4 + 1] = fmaf(xv, w.y, acc[4 * j4 + 1]);
            acc[4 * j4 + 2] = fmaf(xv, w.z, acc[4 * j4 + 2]);
            acc[4 * j4 + 3] = fmaf(xv, w.w, acc[4 * j4 + 3]);
        }
    }
#pragma unroll
    for (int j = 0; j < 64; j++) {
        g_Xp[((size_t)s * G4 + n0 + j) * BATCH + b0 + b] = acc[j] + __ldg(&bo[n0 + j]);
    }
}

// ---- global spin barrier: fresh counter per phase, zeroed by init_kernel ----
__device__ __forceinline__ void bar_sync(unsigned* ctr) {
    __threadfence();
    __syncthreads();
    if (threadIdx.x == 0) {
        atomicAdd(ctr, 1u);
        volatile unsigned* v = ctr;
        while (*v < NCTA) __nanosleep(20);
        __threadfence();
    }
    __syncthreads();
}

__device__ __forceinline__ float sig_(float v) { return 1.0f / (1.0f + expf(-v)); }

// ---- Kernel 2: persistent recurrence; CTA ci owns hidden column ci ----
__global__ __launch_bounds__(256, 1) void rec_kernel(const float* __restrict__ Wh_out,
                                                     const float* __restrict__ Wx_in,
                                                     const float* __restrict__ Wh_in,
                                                     const float* __restrict__ b_in) {
    extern __shared__ float sm[];
    float* sh    = sm;                  // [k][b] staged, k<256, pad 132
    float* w_out = sm + 256 * 132;      // [c][k] 4x128
    float* w_in  = w_out + 512;         // [c][k] 4x256
    float* shg   = w_in + 1024;         // [b][c] 128x4
    float* bis   = shg + 512;           // 4

    const int ci = blockIdx.x;
    const int t  = threadIdx.x;
    const int b  = t & 127;
    const int cp = t >> 7;              // 0:{i,f}  1:{o,g}

    for (int q = t; q < 512; q += 256) {
        int c = q >> 7, k = q & 127;
        w_out[c * 128 + k] = Wh_out[(size_t)k * G4 + c * HID + ci];
    }
    for (int q = t; q < 1024; q += 256) {
        int c = q >> 8, k = q & 255;
        w_in[c * 256 + k] = (k < 128) ? Wx_in[(size_t)k * G4 + c * HID + ci]
                                      : Wh_in[(size_t)(k - 128) * G4 + c * HID + ci];
    }
    if (t < 4) bis[t] = b_in[t * HID + ci];

    float c_reg = 0.f, cn_reg = 0.f, o_reg = 0.f;
    __syncthreads();

    for (int s = 0; s < S_LEN; s++) {
        // stage h: g_h[k][b] -> sh[k*132+b], k<128
        for (int q = t; q < 4096; q += 256) {
            int r = q >> 5, c4 = (q & 31) << 2;
            float4 v = __ldcg((const float4*)g_h + q);
            *(float4*)(sh + r * 132 + c4) = v;
        }
        __syncthreads();

        // outer GEMM: 2 gate columns per thread
        {
            const float4* wa4 = (const float4*)(w_out + (2 * cp) * 128);
            const float4* wb4 = (const float4*)(w_out + (2 * cp + 1) * 128);
            float a0 = 0.f, a1 = 0.f;
#pragma unroll 8
            for (int k4 = 0; k4 < 32; k4++) {
                float4 wa = wa4[k4], wb = wb4[k4];
                float h0 = sh[(4 * k4 + 0) * 132 + b];
                float h1 = sh[(4 * k4 + 1) * 132 + b];
                float h2 = sh[(4 * k4 + 2) * 132 + b];
                float h3 = sh[(4 * k4 + 3) * 132 + b];
                a0 = fmaf(h0, wa.x, a0); a1 = fmaf(h0, wb.x, a1);
                a0 = fmaf(h1, wa.y, a0); a1 = fmaf(h1, wb.y, a1);
                a0 = fmaf(h2, wa.z, a0); a1 = fmaf(h2, wb.z, a1);
                a0 = fmaf(h3, wa.w, a0); a1 = fmaf(h3, wb.w, a1);
            }
            const float* xp = g_Xp + ((size_t)s * G4 + (2 * cp) * HID + ci) * BATCH + b;
            a0 += __ldcs(xp);
            a1 += __ldcs(xp + HID * BATCH);
            shg[b * 4 + 2 * cp]     = a0;
            shg[b * 4 + 2 * cp + 1] = a1;
        }
        __syncthreads();

        // elementwise 1: x_in, h_in
        if (t < 128) {
            float4 gv = *(float4*)(shg + 4 * t);
            float ig = sig_(gv.x), fg = sig_(gv.y);
            o_reg = sig_(gv.z);
            float xin = ig * tanhf(gv.w);
            float hin = fg * c_reg;
            g_xh[ci * BATCH + t]               = xin;
            g_xh[(HID + ci) * BATCH + t]       = hin;
        }
        bar_sync(&g_bar[2 * s]);

        // stage [x_in|h_in]: g_xh[k][b] -> sh[k*132+b], k<256
        for (int q = t; q < 8192; q += 256) {
            int r = q >> 5, c4 = (q & 31) << 2;
            float4 v = __ldcg((const float4*)g_xh + q);
            *(float4*)(sh + r * 132 + c4) = v;
        }
        __syncthreads();

        // inner GEMM: K=256
        {
            const float4* wa4 = (const float4*)(w_in + (2 * cp) * 256);
            const float4* wb4 = (const float4*)(w_in + (2 * cp + 1) * 256);
            float a0 = bis[2 * cp], a1 = bis[2 * cp + 1];
#pragma unroll 8
            for (int k4 = 0; k4 < 64; k4++) {
                float4 wa = wa4[k4], wb = wb4[k4];
                float h0 = sh[(4 * k4 + 0) * 132 + b];
                float h1 = sh[(4 * k4 + 1) * 132 + b];
                float h2 = sh[(4 * k4 + 2) * 132 + b];
                float h3 = sh[(4 * k4 + 3) * 132 + b];
                a0 = fmaf(h0, wa.x, a0); a1 = fmaf(h0, wb.x, a1);
                a0 = fmaf(h1, wa.y, a0); a1 = fmaf(h1, wb.y, a1);
                a0 = fmaf(h2, wa.z, a0); a1 = fmaf(h2, wb.z, a1);
                a0 = fmaf(h3, wa.w, a0); a1 = fmaf(h3, wb.w, a1);
            }
            shg[b * 4 + 2 * cp]     = a0;
            shg[b * 4 + 2 * cp + 1] = a1;
        }
        __syncthreads();

        // elementwise 2: update cn, c, h; publish h
        if (t < 128) {
            float4 gv = *(float4*)(shg + 4 * t);
            float si = sig_(gv.x), sf = sig_(gv.y), so = sig_(gv.z);
            cn_reg = sf * cn_reg + si * tanhf(gv.w);
            float cnew = so * tanhf(cn_reg);
            float hnew = o_reg * tanhf(cnew);
            c_reg = cnew;
            g_h[ci * BATCH + t] = hnew;
            g_hs[((size_t)s * HID + ci) * BATCH + t] = hnew;
        }
        bar_sync(&g_bar[2 * s + 1]);
    }
}

// ---- Kernel 3: out[b][s][o] = b_lin[o] + sum_h hs[s][h][b] * W_lin[o][h] ----
__global__ __launch_bounds__(256) void out_kernel(const float* __restrict__ Wl,
                                                  const float* __restrict__ bl,
                                                  float* __restrict__ out) {
    extern __shared__ float sm[];
    float* hsb = sm;          // [k*128 + b], 16384
    float* wls = sm + 16384;  // [k][o], pad 65

    const int s = blockIdx.x;
    const int t = threadIdx.x;
    const int o = t & 63;
    const int b0 = (t >> 6) * 32;

    const float4* src = (const float4*)(g_hs + (size_t)s * HID * BATCH);
    for (int q = t; q < 4096; q += 256) ((float4*)hsb)[q] = src[q];
    for (int q = t; q < 8192; q += 256) {
        int oo = q >> 7, k = q & 127;
        wls[k * 65 + oo] = Wl[q];
    }
    __syncthreads();

    float acc[32];
#pragma unroll
    for (int j = 0; j < 32; j++) acc[j] = 0.f;

#pragma unroll 2
    for (int k = 0; k < HID; k++) {
        float wv = wls[k * 65 + o];
        const float4* hr = (const float4*)(hsb + k * 128 + b0);
#pragma unroll
        for (int j4 = 0; j4 < 8; j4++) {
            float4 hv = hr[j4];
            acc[4 * j4 + 0] = fmaf(hv.x, wv, acc[4 * j4 + 0]);
            acc[4 * j4 + 1] = fmaf(hv.y, wv, acc[4 * j4 + 1]);
            acc[4 * j4 + 2] = fmaf(hv.z, wv, acc[4 * j4 + 2]);
            acc[4 * j4 + 3] = fmaf(hv.w, wv, acc[4 * j4 + 3]);
        }
    }
    float bb = bl[o];
#pragma unroll
    for (int j = 0; j < 32; j++) {
        out[((size_t)(b0 + j) * S_LEN + s) * OUT_DIM + o] = acc[j] + bb;
    }
}

extern "C" void kernel_launch(void* const* d_in, const int* in_sizes, int n_in,
                              void* d_out, int out_size) {
    const float* x      = (const float*)d_in[0];
    const float* Wx_out = (const float*)d_in[1];
    const float* Wh_out = (const float*)d_in[2];
    const float* b_out  = (const float*)d_in[3];  (void)b_out;  // zeros; folded via bo arg anyway
    const float* Wx_in  = (const float*)d_in[4];
    const float* Wh_in  = (const float*)d_in[5];
    const float* b_in   = (const float*)d_in[6];
    const float* W_lin  = (const float*)d_in[7];
    const float* b_lin  = (const float*)d_in[8];
    float* out = (float*)d_out;

    cudaFuncSetAttribute(rec_kernel, cudaFuncAttributeMaxDynamicSharedMemorySize, REC_SMEM);
    cudaFuncSetAttribute(out_kernel, cudaFuncAttributeMaxDynamicSharedMemorySize, OUT_SMEM);

    init_kernel<<<80, 256>>>();
    xproj_kernel<<<dim3(S_LEN, BATCH / 32), 256>>>(x, Wx_out, (const float*)d_in[3]);
    rec_kernel<<<NCTA, 256, REC_SMEM>>>(Wh_out, Wx_in, Wh_in, b_in);
    out_kernel<<<S_LEN, 256, OUT_SMEM>>>(W_lin, b_lin, out);
}

// round 4
// speedup vs baseline: 1.4089x; 1.4089x over previous
#include <cuda_runtime.h>

#define S_LEN 2048
#define BATCH 128
#define IN_DIM 64
#define HID 128
#define G4 512
#define OUT_DIM 64
#define NGROUP 32
#define CPG 4              // CTAs per group (column slices)
#define BG 4               // batch rows per group
#define NCTA (NGROUP * CPG)

// ---- static device scratch ----
__device__ float g_Xp[(size_t)S_LEN * BATCH * G4];   // [s][b][n]
__device__ float g_hs[(size_t)S_LEN * HID * BATCH];  // [s][h][b]
__device__ float g_h[NGROUP * BG * HID];             // [g][r][h]
__device__ float g_xh[NGROUP * BG * 2 * HID];        // [g][r][k]  (x_in 0..127 | h_in 128..255)
__device__ unsigned g_flag[2 * NCTA];                // [phase][cta] step counters

#define REC_SMEM ((128 * 132 + 128 * 260 + 4 * 260 + 1024 + 512) * 4)
#define OUT_SMEM ((16384 + 128 * 65) * 4)

__global__ void init_kernel() {
    int t = blockIdx.x * blockDim.x + threadIdx.x;
    if (t < 2 * NCTA) g_flag[t] = 0u;
    if (t < NGROUP * BG * HID) g_h[t] = 0.0f;
}

// ---- Kernel 1: Xp[s][b][n] = b_out[n] + sum_i x[b][i][s] * Wx_out[i][n] ----
__global__ __launch_bounds__(256) void xproj_kernel(const float* __restrict__ x,
                                                    const float* __restrict__ Wx,
                                                    const float* __restrict__ bo) {
    __shared__ float xs[IN_DIM * 33];  // [i][b]
    const int s = blockIdx.x;
    const int b0 = blockIdx.y * 32;
    const int t = threadIdx.x;
    const int b = t & 31;
    const int n0 = (t >> 5) * 64;

    for (int q = t; q < 32 * IN_DIM; q += 256) {
        int bb = q >> 6, i = q & 63;
        xs[i * 33 + bb] = x[((size_t)(b0 + bb) * IN_DIM + i) * S_LEN + s];
    }
    __syncthreads();

    float acc[64];
#pragma unroll
    for (int j = 0; j < 64; j++) acc[j] = 0.f;

#pragma unroll 2
    for (int k = 0; k < IN_DIM; k++) {
        float xv = xs[k * 33 + b];
        const float4* wr = (const float4*)(Wx + (size_t)k * G4 + n0);
#pragma unroll
        for (int j4 = 0; j4 < 16; j4++) {
            float4 w = __ldg(&wr[j4]);
            acc[4 * j4 + 0] = fmaf(xv, w.x, acc[4 * j4 + 0]);
            acc[4 * j4 + 1] = fmaf(xv, w.y, acc[4 * j4 + 1]);
            acc[4 * j4 + 2] = fmaf(xv, w.z, acc[4 * j4 + 2]);
            acc[4 * j4 + 3] = fmaf(xv, w.w, acc[4 * j4 + 3]);
        }
    }
#pragma unroll
    for (int j = 0; j < 64; j++) {
        g_Xp[((size_t)s * BATCH + b0 + b) * G4 + n0 + j] = acc[j] + __ldg(&bo[n0 + j]);
    }
}

__device__ __forceinline__ float sigf(float v) { return 1.0f / (1.0f + __expf(-v)); }

__device__ __forceinline__ void group_wait(int gbase, unsigned tgt) {
    if (threadIdx.x < 32) {
        volatile unsigned* f = g_flag;
        for (;;) {
            unsigned v = (threadIdx.x < CPG) ? f[gbase + threadIdx.x] : tgt;
            if (__all_sync(0xffffffffu, v >= tgt)) break;
            __nanosleep(20);
        }
    }
    __syncthreads();
}

// ---- Kernel 2: persistent recurrence; group g = 4 batch rows, CTA slice cs = 32 hidden cols ----
__global__ __launch_bounds__(256, 1) void rec_kernel(const float* __restrict__ Wh_out,
                                                     const float* __restrict__ Wx_in,
                                                     const float* __restrict__ Wh_in,
                                                     const float* __restrict__ b_in) {
    extern __shared__ float sm[];
    float* w_out = sm;                     // [j][k] 128 x 132 (pad)
    float* w_in  = w_out + 128 * 132;      // [j][k] 128 x 260 (pad)
    float* sh    = w_in + 128 * 260;       // staged [r][k] 4 x 260
    float* sgp   = sh + 4 * 260;           // partials [kh][j][r] 2*128*4
    float* sg    = sgp + 1024;             // gates [r][j] 4*128

    const int cta = blockIdx.x;
    const int g   = cta >> 2;
    const int cs  = cta & 3;
    const int t   = threadIdx.x;
    const int j   = t & 127;               // local gate col
    const int kh  = t >> 7;                // k-half
    const int gcol = (j >> 5) * 128 + cs * 32 + (j & 31);  // global gate col

    // resident weights (one-time): w[j][k], coalesced global reads
    for (int q = t; q < 128 * 128; q += 256) {
        int c = q & 127, k = q >> 7;
        int gc = (c >> 5) * 128 + cs * 32 + (c & 31);
        w_out[c * 132 + k] = Wh_out[(size_t)k * G4 + gc];
    }
    for (int q = t; q < 128 * 256; q += 256) {
        int c = q & 127, k = q >> 7;
        int gc = (c >> 5) * 128 + cs * 32 + (c & 31);
        w_in[c * 260 + k] = (k < 128) ? Wx_in[(size_t)k * G4 + gc]
                                      : Wh_in[(size_t)(k - 128) * G4 + gc];
    }
    float bin = (t < 128) ? b_in[gcol] : 0.f;

    // per-(b,h) state in threads t<128: bl = t>>5, hc = t&31
    const int bl = t >> 5, hc = t & 31;
    const int h_own = cs * 32 + hc;
    float c_reg = 0.f, cn_reg = 0.f, o_reg = 0.f;
    __syncthreads();

    for (int s = 0; s < S_LEN; s++) {
        // prefetch Xp (consumed ~1.3K cyc later in the reduction phase)
        float xp0 = 0.f, xp1 = 0.f, xp2 = 0.f, xp3 = 0.f;
        if (t < 128) {
            const float* xp = g_Xp + ((size_t)s * BATCH + g * BG) * G4 + gcol;
            xp0 = __ldcs(xp);
            xp1 = __ldcs(xp + G4);
            xp2 = __ldcs(xp + 2 * G4);
            xp3 = __ldcs(xp + 3 * G4);
        }
        // stage h: g_h[g][r][0:128] -> sh[r][k]
        if (t < 128) {
            float4 v = __ldcg((const float4*)(g_h + g * (BG * HID)) + t);
            *(float4*)(sh + (t >> 5) * 260 + (t & 31) * 4) = v;
        }
        __syncthreads();

        // outer GEMM: acc[r] for col j over k-half kh
        {
            const float4* wp = (const float4*)(w_out + j * 132) + kh * 16;
            const float4* h0 = (const float4*)(sh + 0 * 260) + kh * 16;
            const float4* h1 = (const float4*)(sh + 1 * 260) + kh * 16;
            const float4* h2 = (const float4*)(sh + 2 * 260) + kh * 16;
            const float4* h3 = (const float4*)(sh + 3 * 260) + kh * 16;
            float a0 = 0.f, a1 = 0.f, a2 = 0.f, a3 = 0.f;
#pragma unroll 8
            for (int q = 0; q < 16; q++) {
                float4 w = wp[q];
                float4 x0 = h0[q], x1 = h1[q], x2 = h2[q], x3 = h3[q];
                a0 = fmaf(w.x, x0.x, a0); a0 = fmaf(w.y, x0.y, a0);
                a0 = fmaf(w.z, x0.z, a0); a0 = fmaf(w.w, x0.w, a0);
                a1 = fmaf(w.x, x1.x, a1); a1 = fmaf(w.y, x1.y, a1);
                a1 = fmaf(w.z, x1.z, a1); a1 = fmaf(w.w, x1.w, a1);
                a2 = fmaf(w.x, x2.x, a2); a2 = fmaf(w.y, x2.y, a2);
                a2 = fmaf(w.z, x2.z, a2); a2 = fmaf(w.w, x2.w, a2);
                a3 = fmaf(w.x, x3.x, a3); a3 = fmaf(w.y, x3.y, a3);
                a3 = fmaf(w.z, x3.z, a3); a3 = fmaf(w.w, x3.w, a3);
            }
            *(float4*)(sgp + (kh * 128 + j) * 4) = make_float4(a0, a1, a2, a3);
        }
        __syncthreads();
        if (t < 128) {  // reduce halves + Xp
            float4 p = *(const float4*)(sgp + j * 4);
            float4 q = *(const float4*)(sgp + (128 + j) * 4);
            sg[0 * 128 + j] = p.x + q.x + xp0;
            sg[1 * 128 + j] = p.y + q.y + xp1;
            sg[2 * 128 + j] = p.z + q.z + xp2;
            sg[3 * 128 + j] = p.w + q.w + xp3;
        }
        __syncthreads();

        // elementwise 1: publish x_in, h_in for (b = g*4+bl, h = h_own)
        if (t < 128) {
            float i_ = sigf(sg[bl * 128 + hc]);
            float f_ = sigf(sg[bl * 128 + 32 + hc]);
            o_reg    = sigf(sg[bl * 128 + 64 + hc]);
            float g_ = tanhf(sg[bl * 128 + 96 + hc]);
            float* dst = g_xh + (g * BG + bl) * 256 + h_own;
            dst[0]   = i_ * g_;
            dst[128] = f_ * c_reg;
            __threadfence();
        }
        __syncthreads();
        if (t == 0) *(volatile unsigned*)&g_flag[cta] = (unsigned)(s + 1);
        group_wait(g * 4, (unsigned)(s + 1));

        // stage xh: g_xh[g][r][0:256] -> sh[r][k]
        {
            float4 v = __ldcg((const float4*)(g_xh + g * (BG * 2 * HID)) + t);
            *(float4*)(sh + (t >> 6) * 260 + (t & 63) * 4) = v;
        }
        __syncthreads();

        // inner GEMM: K=256, half per kh
        {
            const float4* wp = (const float4*)(w_in + j * 260) + kh * 32;
            const float4* h0 = (const float4*)(sh + 0 * 260) + kh * 32;
            const float4* h1 = (const float4*)(sh + 1 * 260) + kh * 32;
            const float4* h2 = (const float4*)(sh + 2 * 260) + kh * 32;
            const float4* h3 = (const float4*)(sh + 3 * 260) + kh * 32;
            float a0 = 0.f, a1 = 0.f, a2 = 0.f, a3 = 0.f;
#pragma unroll 8
            for (int q = 0; q < 32; q++) {
                float4 w = wp[q];
                float4 x0 = h0[q], x1 = h1[q], x2 = h2[q], x3 = h3[q];
                a0 = fmaf(w.x, x0.x, a0); a0 = fmaf(w.y, x0.y, a0);
                a0 = fmaf(w.z, x0.z, a0); a0 = fmaf(w.w, x0.w, a0);
                a1 = fmaf(w.x, x1.x, a1); a1 = fmaf(w.y, x1.y, a1);
                a1 = fmaf(w.z, x1.z, a1); a1 = fmaf(w.w, x1.w, a1);
                a2 = fmaf(w.x, x2.x, a2); a2 = fmaf(w.y, x2.y, a2);
                a2 = fmaf(w.z, x2.z, a2); a2 = fmaf(w.w, x2.w, a2);
                a3 = fmaf(w.x, x3.x, a3); a3 = fmaf(w.y, x3.y, a3);
                a3 = fmaf(w.z, x3.z, a3); a3 = fmaf(w.w, x3.w, a3);
            }
            *(float4*)(sgp + (kh * 128 + j) * 4) = make_float4(a0, a1, a2, a3);
        }
        __syncthreads();
        if (t < 128) {
            float4 p = *(const float4*)(sgp + j * 4);
            float4 q = *(const float4*)(sgp + (128 + j) * 4);
            sg[0 * 128 + j] = p.x + q.x + bin;
            sg[1 * 128 + j] = p.y + q.y + bin;
            sg[2 * 128 + j] = p.z + q.z + bin;
            sg[3 * 128 + j] = p.w + q.w + bin;
        }
        __syncthreads();

        // elementwise 2: update cn, c; publish h
        if (t < 128) {
            float ii = sigf(sg[bl * 128 + hc]);
            float fi = sigf(sg[bl * 128 + 32 + hc]);
            float oi = sigf(sg[bl * 128 + 64 + hc]);
            float gg = tanhf(sg[bl * 128 + 96 + hc]);
            cn_reg = fi * cn_reg + ii * gg;
            c_reg  = oi * tanhf(cn_reg);
            float hnew = o_reg * tanhf(c_reg);
            g_h[(g * BG + bl) * HID + h_own] = hnew;
            g_hs[((size_t)s * HID + h_own) * BATCH + g * BG + bl] = hnew;
            __threadfence();
        }
        __syncthreads();
        if (t == 0) *(volatile unsigned*)&g_flag[NCTA + cta] = (unsigned)(s + 1);
        group_wait(NCTA + g * 4, (unsigned)(s + 1));
    }
}

// ---- Kernel 3: out[b][s][o] = b_lin[o] + sum_h hs[s][h][b] * W_lin[o][h] ----
__global__ __launch_bounds__(256) void out_kernel(const float* __restrict__ Wl,
                                                  const float* __restrict__ bl,
                                                  float* __restrict__ out) {
    extern __shared__ float sm[];
    float* hsb = sm;          // [h*128 + b]
    float* wls = sm + 16384;  // [h][o] pad 65

    const int s = blockIdx.x;
    const int t = threadIdx.x;
    const int o = t & 63;
    const int b0 = (t >> 6) * 32;

    const float4* src = (const float4*)(g_hs + (size_t)s * HID * BATCH);
    for (int q = t; q < 4096; q += 256) ((float4*)hsb)[q] = src[q];
    for (int q = t; q < 8192; q += 256) {
        int oo = q >> 7, k = q & 127;
        wls[k * 65 + oo] = Wl[q];
    }
    __syncthreads();

    float acc[32];
#pragma unroll
    for (int j = 0; j < 32; j++) acc[j] = 0.f;

#pragma unroll 2
    for (int k = 0; k < HID; k++) {
        float wv = wls[k * 65 + o];
        const float4* hr = (const float4*)(hsb + k * 128 + b0);
#pragma unroll
        for (int j4 = 0; j4 < 8; j4++) {
            float4 hv = hr[j4];
            acc[4 * j4 + 0] = fmaf(hv.x, wv, acc[4 * j4 + 0]);
            acc[4 * j4 + 1] = fmaf(hv.y, wv, acc[4 * j4 + 1]);
            acc[4 * j4 + 2] = fmaf(hv.z, wv, acc[4 * j4 + 2]);
            acc[4 * j4 + 3] = fmaf(hv.w, wv, acc[4 * j4 + 3]);
        }
    }
    float bb = bl[o];
#pragma unroll
    for (int j = 0; j < 32; j++) {
        out[((size_t)(b0 + j) * S_LEN + s) * OUT_DIM + o] = acc[j] + bb;
    }
}

extern "C" void kernel_launch(void* const* d_in, const int* in_sizes, int n_in,
                              void* d_out, int out_size) {
    const float* x      = (const float*)d_in[0];
    const float* Wx_out = (const float*)d_in[1];
    const float* Wh_out = (const float*)d_in[2];
    const float* b_out  = (const float*)d_in[3];
    const float* Wx_in  = (const float*)d_in[4];
    const float* Wh_in  = (const float*)d_in[5];
    const float* b_in   = (const float*)d_in[6];
    const float* W_lin  = (const float*)d_in[7];
    const float* b_lin  = (const float*)d_in[8];
    float* out = (float*)d_out;

    cudaFuncSetAttribute(rec_kernel, cudaFuncAttributeMaxDynamicSharedMemorySize, REC_SMEM);
    cudaFuncSetAttribute(out_kernel, cudaFuncAttributeMaxDynamicSharedMemorySize, OUT_SMEM);

    init_kernel<<<80, 256>>>();
    xproj_kernel<<<dim3(S_LEN, BATCH / 32), 256>>>(x, Wx_out, b_out);
    rec_kernel<<<NCTA, 256, REC_SMEM>>>(Wh_out, Wx_in, Wh_in, b_in);
    out_kernel<<<S_LEN, 256, OUT_SMEM>>>(W_lin, b_lin, out);
}

// round 5
// speedup vs baseline: 1.8326x; 1.3007x over previous
#include <cuda_runtime.h>
#include <cstdint>

#define S_LEN 2048
#define BATCH 128
#define IN_DIM 64
#define HID 128
#define G4 512
#define OUT_DIM 64
#define NGROUP 32
#define CPG 4
#define BG 4
#define NCTA (NGROUP * CPG)

// ---- static device scratch ----
__device__ float g_Xp[(size_t)S_LEN * BATCH * G4];   // [s][b][n]
__device__ float g_hs[(size_t)S_LEN * HID * BATCH];  // [s][h][b]

// ---- rec smem layout (float offsets) ----
#define W_OUT_OFF 0                           // [j][k] 128 x 132 (pad)
#define W_IN_OFF  (128 * 132)                 // [j][k] 128 x 260 (pad)
#define SH_H_OFF  (W_IN_OFF + 128 * 260)      // [k][r] 128 x 4
#define SH_XH_OFF (SH_H_OFF + 512)            // [k][r] 256 x 4
#define SGP_OFF   (SH_XH_OFF + 1024)          // partials [kh][j] x float4
#define SG_OFF    (SGP_OFF + 1024)            // gates [r][j] 4 x 128
#define REC_SMEM  ((SG_OFF + 512) * 4)        // 212,992 B
#define OUT_SMEM  ((16384 + 128 * 65) * 4)

__device__ __forceinline__ float sigf(float v) { return 1.0f / (1.0f + __expf(-v)); }

__device__ __forceinline__ uint32_t smem_u32(const void* p) {
    uint32_t a;
    asm("{ .reg .u64 t; cvta.to.shared.u64 t, %1; cvt.u32.u64 %0, t; }" : "=r"(a) : "l"(p));
    return a;
}
__device__ __forceinline__ uint32_t mapa_u32(uint32_t local_addr, int rank) {
    uint32_t r;
    asm("mapa.shared::cluster.u32 %0, %1, %2;" : "=r"(r) : "r"(local_addr), "r"(rank));
    return r;
}
__device__ __forceinline__ void st_cluster_f32(uint32_t addr, float v) {
    asm volatile("st.shared::cluster.f32 [%0], %1;" :: "r"(addr), "f"(v) : "memory");
}
#define CLUSTER_SYNC_() do { \
    asm volatile("barrier.cluster.arrive.aligned;" ::: "memory"); \
    asm volatile("barrier.cluster.wait.aligned;" ::: "memory"); \
} while (0)

__device__ __forceinline__ void ffma2(unsigned long long& d, unsigned long long a, unsigned long long b) {
    asm("fma.rn.f32x2 %0, %1, %2, %0;" : "+l"(d) : "l"(a), "l"(b));
}
__device__ __forceinline__ unsigned long long packw(float w) {
    unsigned long long p;
    asm("mov.b64 %0, {%1, %1};" : "=l"(p) : "r"(__float_as_uint(w)));
    return p;
}

// ---- Kernel 1: Xp[s][b][n] = b_out[n] + sum_i x[b][i][s] * Wx_out[i][n] ----
__global__ __launch_bounds__(256) void xproj_kernel(const float* __restrict__ x,
                                                    const float* __restrict__ Wx,
                                                    const float* __restrict__ bo) {
    __shared__ float xs[IN_DIM * 33];
    const int s = blockIdx.x;
    const int b0 = blockIdx.y * 32;
    const int t = threadIdx.x;
    const int b = t & 31;
    const int n0 = (t >> 5) * 64;

    for (int q = t; q < 32 * IN_DIM; q += 256) {
        int bb = q >> 6, i = q & 63;
        xs[i * 33 + bb] = x[((size_t)(b0 + bb) * IN_DIM + i) * S_LEN + s];
    }
    __syncthreads();

    float acc[64];
#pragma unroll
    for (int j = 0; j < 64; j++) acc[j] = 0.f;
#pragma unroll 2
    for (int k = 0; k < IN_DIM; k++) {
        float xv = xs[k * 33 + b];
        const float4* wr = (const float4*)(Wx + (size_t)k * G4 + n0);
#pragma unroll
        for (int j4 = 0; j4 < 16; j4++) {
            float4 w = __ldg(&wr[j4]);
            acc[4 * j4 + 0] = fmaf(xv, w.x, acc[4 * j4 + 0]);
            acc[4 * j4 + 1] = fmaf(xv, w.y, acc[4 * j4 + 1]);
            acc[4 * j4 + 2] = fmaf(xv, w.z, acc[4 * j4 + 2]);
            acc[4 * j4 + 3] = fmaf(xv, w.w, acc[4 * j4 + 3]);
        }
    }
#pragma unroll
    for (int j = 0; j < 64; j++) {
        g_Xp[((size_t)s * BATCH + b0 + b) * G4 + n0 + j] = acc[j] + __ldg(&bo[n0 + j]);
    }
}

// ---- Kernel 2: persistent recurrence; cluster of 4 CTAs = 1 group (4 batch rows) ----
__global__ __launch_bounds__(256, 1) __cluster_dims__(CPG, 1, 1)
void rec_kernel(const float* __restrict__ Wh_out,
                const float* __restrict__ Wx_in,
                const float* __restrict__ Wh_in,
                const float* __restrict__ b_in) {
    extern __shared__ float sm[];
    float* w_out = sm + W_OUT_OFF;
    float* w_in  = sm + W_IN_OFF;
    float* sh_h  = sm + SH_H_OFF;
    float* sh_xh = sm + SH_XH_OFF;
    float* sgp   = sm + SGP_OFF;
    float* sg    = sm + SG_OFF;

    const int cta = blockIdx.x;
    const int g   = cta >> 2;
    const int cs  = cta & 3;            // cluster rank = column slice
    const int t   = threadIdx.x;
    const int j   = t & 127;            // local gate column
    const int kh  = t >> 7;             // k-half
    const int gcol = (j >> 5) * 128 + cs * 32 + (j & 31);

    // resident weights [j][k]
    for (int q = t; q < 128 * 128; q += 256) {
        int c = q & 127, k = q >> 7;
        int gc = (c >> 5) * 128 + cs * 32 + (c & 31);
        w_out[c * 132 + k] = Wh_out[(size_t)k * G4 + gc];
    }
    for (int q = t; q < 128 * 256; q += 256) {
        int c = q & 127, k = q >> 7;
        int gc = (c >> 5) * 128 + cs * 32 + (c & 31);
        w_in[c * 260 + k] = (k < 128) ? Wx_in[(size_t)k * G4 + gc]
                                      : Wh_in[(size_t)(k - 128) * G4 + gc];
    }
    float bin = (t < 128) ? b_in[gcol] : 0.f;

    // zero initial h stage (h0 = 0)
    for (int q = t; q < 512; q += 256) sh_h[q] = 0.f;

    // precompute peer SMEM addresses for exchange buffers
    uint32_t my_h  = smem_u32(sh_h);
    uint32_t my_xh = smem_u32(sh_xh);
    uint32_t peer_h[CPG], peer_xh[CPG];
#pragma unroll
    for (int r = 0; r < CPG; r++) {
        peer_h[r]  = mapa_u32(my_h, r);
        peer_xh[r] = mapa_u32(my_xh, r);
    }

    const int bl = t >> 5, hc = t & 31;          // for t<128: batch row, own hidden col
    const int h_own = cs * 32 + hc;
    float c_reg = 0.f, cn_reg = 0.f, o_reg = 0.f;

    __syncthreads();
    CLUSTER_SYNC_();

    for (int s = 0; s < S_LEN; s++) {
        // prefetch Xp (consumed after outer GEMM)
        float xp0 = 0.f, xp1 = 0.f, xp2 = 0.f, xp3 = 0.f;
        if (t < 128) {
            const float* xp = g_Xp + ((size_t)s * BATCH + g * BG) * G4 + gcol;
            xp0 = __ldcs(xp);
            xp1 = __ldcs(xp + G4);
            xp2 = __ldcs(xp + 2 * G4);
            xp3 = __ldcs(xp + 3 * G4);
        }

        // ---- outer GEMM: K=128, half per kh; f32x2 packed over batch rows ----
        {
            const float4* wp = (const float4*)(w_out + j * 132) + kh * 16;
            const ulonglong2* hp = (const ulonglong2*)sh_h + kh * 64;
            unsigned long long a01 = 0ull, a23 = 0ull;
#pragma unroll
            for (int q = 0; q < 16; q++) {
                float4 w = wp[q];
                ulonglong2 h0 = hp[4 * q + 0], h1 = hp[4 * q + 1];
                ulonglong2 h2 = hp[4 * q + 2], h3 = hp[4 * q + 3];
                unsigned long long wk;
                wk = packw(w.x); ffma2(a01, wk, h0.x); ffma2(a23, wk, h0.y);
                wk = packw(w.y); ffma2(a01, wk, h1.x); ffma2(a23, wk, h1.y);
                wk = packw(w.z); ffma2(a01, wk, h2.x); ffma2(a23, wk, h2.y);
                wk = packw(w.w); ffma2(a01, wk, h3.x); ffma2(a23, wk, h3.y);
            }
            ulonglong2 acc; acc.x = a01; acc.y = a23;
            *(ulonglong2*)(sgp + (kh * 128 + j) * 4) = acc;
        }
        __syncthreads();
        if (t < 128) {  // reduce halves + Xp
            float4 p = *(const float4*)(sgp + j * 4);
            float4 q = *(const float4*)(sgp + (128 + j) * 4);
            sg[0 * 128 + j] = p.x + q.x + xp0;
            sg[1 * 128 + j] = p.y + q.y + xp1;
            sg[2 * 128 + j] = p.z + q.z + xp2;
            sg[3 * 128 + j] = p.w + q.w + xp3;
        }
        __syncthreads();

        // ---- elementwise 1: push x_in, h_in into all 4 peers' sh_xh ----
        if (t < 128) {
            float i_ = sigf(sg[bl * 128 + hc]);
            float f_ = sigf(sg[bl * 128 + 32 + hc]);
            o_reg    = sigf(sg[bl * 128 + 64 + hc]);
            float g_ = tanhf(sg[bl * 128 + 96 + hc]);
            float xin = i_ * g_;
            float hin = f_ * c_reg;
            uint32_t off0 = (uint32_t)(h_own * 4 + bl) * 4u;
            uint32_t off1 = (uint32_t)((128 + h_own) * 4 + bl) * 4u;
#pragma unroll
            for (int r = 0; r < CPG; r++) {
                st_cluster_f32(peer_xh[r] + off0, xin);
                st_cluster_f32(peer_xh[r] + off1, hin);
            }
        }
        CLUSTER_SYNC_();

        // ---- inner GEMM: K=256, half per kh ----
        {
            const float4* wp = (const float4*)(w_in + j * 260) + kh * 32;
            const ulonglong2* hp = (const ulonglong2*)sh_xh + kh * 128;
            unsigned long long a01 = 0ull, a23 = 0ull;
#pragma unroll 8
            for (int q = 0; q < 32; q++) {
                float4 w = wp[q];
                ulonglong2 h0 = hp[4 * q + 0], h1 = hp[4 * q + 1];
                ulonglong2 h2 = hp[4 * q + 2], h3 = hp[4 * q + 3];
                unsigned long long wk;
                wk = packw(w.x); ffma2(a01, wk, h0.x); ffma2(a23, wk, h0.y);
                wk = packw(w.y); ffma2(a01, wk, h1.x); ffma2(a23, wk, h1.y);
                wk = packw(w.z); ffma2(a01, wk, h2.x); ffma2(a23, wk, h2.y);
                wk = packw(w.w); ffma2(a01, wk, h3.x); ffma2(a23, wk, h3.y);
            }
            ulonglong2 acc; acc.x = a01; acc.y = a23;
            *(ulonglong2*)(sgp + (kh * 128 + j) * 4) = acc;
        }
        __syncthreads();
        if (t < 128) {
            float4 p = *(const float4*)(sgp + j * 4);
            float4 q = *(const float4*)(sgp + (128 + j) * 4);
            sg[0 * 128 + j] = p.x + q.x + bin;
            sg[1 * 128 + j] = p.y + q.y + bin;
            sg[2 * 128 + j] = p.z + q.z + bin;
            sg[3 * 128 + j] = p.w + q.w + bin;
        }
        __syncthreads();

        // ---- elementwise 2: update state; push h into all 4 peers' sh_h ----
        if (t < 128) {
            float ii = sigf(sg[bl * 128 + hc]);
            float fi = sigf(sg[bl * 128 + 32 + hc]);
            float oi = sigf(sg[bl * 128 + 64 + hc]);
            float gg = tanhf(sg[bl * 128 + 96 + hc]);
            cn_reg = fi * cn_reg + ii * gg;
            c_reg  = oi * tanhf(cn_reg);
            float hnew = o_reg * tanhf(c_reg);
            uint32_t offh = (uint32_t)(h_own * 4 + bl) * 4u;
#pragma unroll
            for (int r = 0; r < CPG; r++) st_cluster_f32(peer_h[r] + offh, hnew);
            g_hs[((size_t)s * HID + h_own) * BATCH + g * BG + bl] = hnew;
        }
        CLUSTER_SYNC_();
    }
}

// ---- Kernel 3: out[b][s][o] = b_lin[o] + sum_h hs[s][h][b] * W_lin[o][h] ----
__global__ __launch_bounds__(256) void out_kernel(const float* __restrict__ Wl,
                                                  const float* __restrict__ bl,
                                                  float* __restrict__ out) {
    extern __shared__ float sm[];
    float* hsb = sm;
    float* wls = sm + 16384;

    const int s = blockIdx.x;
    const int t = threadIdx.x;
    const int o = t & 63;
    const int b0 = (t >> 6) * 32;

    const float4* src = (const float4*)(g_hs + (size_t)s * HID * BATCH);
    for (int q = t; q < 4096; q += 256) ((float4*)hsb)[q] = src[q];
    for (int q = t; q < 8192; q += 256) {
        int oo = q >> 7, k = q & 127;
        wls[k * 65 + oo] = Wl[q];
    }
    __syncthreads();

    float acc[32];
#pragma unroll
    for (int jj = 0; jj < 32; jj++) acc[jj] = 0.f;
#pragma unroll 2
    for (int k = 0; k < HID; k++) {
        float wv = wls[k * 65 + o];
        const float4* hr = (const float4*)(hsb + k * 128 + b0);
#pragma unroll
        for (int j4 = 0; j4 < 8; j4++) {
            float4 hv = hr[j4];
            acc[4 * j4 + 0] = fmaf(hv.x, wv, acc[4 * j4 + 0]);
            acc[4 * j4 + 1] = fmaf(hv.y, wv, acc[4 * j4 + 1]);
            acc[4 * j4 + 2] = fmaf(hv.z, wv, acc[4 * j4 + 2]);
            acc[4 * j4 + 3] = fmaf(hv.w, wv, acc[4 * j4 + 3]);
        }
    }
    float bb = bl[o];
#pragma unroll
    for (int jj = 0; jj < 32; jj++) {
        out[((size_t)(b0 + jj) * S_LEN + s) * OUT_DIM + o] = acc[jj] + bb;
    }
}

extern "C" void kernel_launch(void* const* d_in, const int* in_sizes, int n_in,
                              void* d_out, int out_size) {
    const float* x      = (const float*)d_in[0];
    const float* Wx_out = (const float*)d_in[1];
    const float* Wh_out = (const float*)d_in[2];
    const float* b_out  = (const float*)d_in[3];
    const float* Wx_in  = (const float*)d_in[4];
    const float* Wh_in  = (const float*)d_in[5];
    const float* b_in   = (const float*)d_in[6];
    const float* W_lin  = (const float*)d_in[7];
    const float* b_lin  = (const float*)d_in[8];
    float* out = (float*)d_out;

    cudaFuncSetAttribute(rec_kernel, cudaFuncAttributeMaxDynamicSharedMemorySize, REC_SMEM);
    cudaFuncSetAttribute(out_kernel, cudaFuncAttributeMaxDynamicSharedMemorySize, OUT_SMEM);

    xproj_kernel<<<dim3(S_LEN, BATCH / 32), 256>>>(x, Wx_out, b_out);
    rec_kernel<<<NCTA, 256, REC_SMEM>>>(Wh_out, Wx_in, Wh_in, b_in);
    out_kernel<<<S_LEN, 256, OUT_SMEM>>>(W_lin, b_lin, out);
}

// round 6
// speedup vs baseline: 2.3544x; 1.2848x over previous
#include <cuda_runtime.h>
#include <cstdint>

#define S_LEN 2048
#define BATCH 128
#define IN_DIM 64
#define HID 128
#define G4 512
#define OUT_DIM 64
#define NGROUP 32
#define CPG 4
#define BG 4
#define NCTA (NGROUP * CPG)

// ---- static device scratch ----
__device__ float g_Xp[(size_t)S_LEN * BATCH * G4];   // [s][b][n]
__device__ float g_hs[(size_t)S_LEN * HID * BATCH];  // [s][h][b]

#define OUT_SMEM ((16384 + 128 * 65) * 4)

__device__ __forceinline__ float sigf(float v) { return 1.0f / (1.0f + __expf(-v)); }

__device__ __forceinline__ uint32_t smem_u32(const void* p) {
    uint32_t a;
    asm("{ .reg .u64 t; cvta.to.shared.u64 t, %1; cvt.u32.u64 %0, t; }" : "=r"(a) : "l"(p));
    return a;
}
__device__ __forceinline__ uint32_t mapa_u32(uint32_t local_addr, int rank) {
    uint32_t r;
    asm("mapa.shared::cluster.u32 %0, %1, %2;" : "=r"(r) : "r"(local_addr), "r"(rank));
    return r;
}
__device__ __forceinline__ void st_cluster_f32(uint32_t addr, float v) {
    asm volatile("st.shared::cluster.f32 [%0], %1;" :: "r"(addr), "f"(v) : "memory");
}
#define CLUSTER_SYNC_() do { \
    asm volatile("barrier.cluster.arrive.aligned;" ::: "memory"); \
    asm volatile("barrier.cluster.wait.aligned;" ::: "memory"); \
} while (0)

__device__ __forceinline__ void ffma2(unsigned long long& d, unsigned long long a, unsigned long long b) {
    asm("fma.rn.f32x2 %0, %1, %2, %0;" : "+l"(d) : "l"(a), "l"(b));
}
__device__ __forceinline__ unsigned long long pack2(float a, float b) {
    unsigned long long p;
    asm("mov.b64 %0, {%1, %2};" : "=l"(p) : "f"(a), "f"(b));
    return p;
}
__device__ __forceinline__ float sum2(unsigned long long p) {
    float lo, hi;
    asm("mov.b64 {%0, %1}, %2;" : "=f"(lo), "=f"(hi) : "l"(p));
    return lo + hi;
}

// ---- Kernel 1: Xp[s][b][n] = b_out[n] + sum_i x[b][i][s] * Wx_out[i][n] ----
__global__ __launch_bounds__(256) void xproj_kernel(const float* __restrict__ x,
                                                    const float* __restrict__ Wx,
                                                    const float* __restrict__ bo) {
    __shared__ float xs[IN_DIM * 33];
    const int s = blockIdx.x;
    const int b0 = blockIdx.y * 32;
    const int t = threadIdx.x;
    const int b = t & 31;
    const int n0 = (t >> 5) * 64;

    for (int q = t; q < 32 * IN_DIM; q += 256) {
        int bb = q >> 6, i = q & 63;
        xs[i * 33 + bb] = x[((size_t)(b0 + bb) * IN_DIM + i) * S_LEN + s];
    }
    __syncthreads();

    float acc[64];
#pragma unroll
    for (int j = 0; j < 64; j++) acc[j] = 0.f;
#pragma unroll 2
    for (int k = 0; k < IN_DIM; k++) {
        float xv = xs[k * 33 + b];
        const float4* wr = (const float4*)(Wx + (size_t)k * G4 + n0);
#pragma unroll
        for (int j4 = 0; j4 < 16; j4++) {
            float4 w = __ldg(&wr[j4]);
            acc[4 * j4 + 0] = fmaf(xv, w.x, acc[4 * j4 + 0]);
            acc[4 * j4 + 1] = fmaf(xv, w.y, acc[4 * j4 + 1]);
            acc[4 * j4 + 2] = fmaf(xv, w.z, acc[4 * j4 + 2]);
            acc[4 * j4 + 3] = fmaf(xv, w.w, acc[4 * j4 + 3]);
        }
    }
#pragma unroll
    for (int j = 0; j < 64; j++) {
        g_Xp[((size_t)s * BATCH + b0 + b) * G4 + n0 + j] = acc[j] + __ldg(&bo[n0 + j]);
    }
}

// ---- Kernel 2: persistent recurrence; cluster of 4 CTAs = 1 group (4 batch rows).
//      Weights register-resident; FFMA2 packed over k-parity; shfl reduction. ----
__global__ __launch_bounds__(256, 1) __cluster_dims__(CPG, 1, 1)
void rec_kernel(const float* __restrict__ Wh_out,
                const float* __restrict__ Wx_in,
                const float* __restrict__ Wh_in,
                const float* __restrict__ b_in) {
    // exchange buffers: [r][chunk][68] (68-float chunks: 64 data + 4 pad)
    __shared__ __align__(16) float sh_h[BG * 2 * 68];    // k < 128
    __shared__ __align__(16) float sh_xh[BG * 4 * 68];   // k < 256
    __shared__ float sg[BG * 128];                       // gates [r][j]

    const int cta = blockIdx.x;
    const int g   = cta >> 2;
    const int cs  = cta & 3;           // cluster rank = hidden-column slice
    const int t   = threadIdx.x;
    const int j   = t >> 1;            // gate column 0..127
    const int kp  = t & 1;             // K-half
    const int gcol = (j >> 5) * 128 + cs * 32 + (j & 31);

    // ---- register-resident weights, k-pairs packed ----
    unsigned long long wo[32];   // outer: k = kp*64 + 2q
    unsigned long long wi[64];   // inner: k = kp*128 + 2q (kp0 -> Wx_in, kp1 -> Wh_in)
    {
        const float* wbase = Wh_out + (size_t)(kp * 64) * G4 + gcol;
#pragma unroll
        for (int q = 0; q < 32; q++)
            wo[q] = pack2(wbase[(size_t)(2 * q) * G4], wbase[(size_t)(2 * q + 1) * G4]);
        const float* ibase = (kp ? Wh_in : Wx_in) + gcol;
#pragma unroll
        for (int q = 0; q < 64; q++)
            wi[q] = pack2(ibase[(size_t)(2 * q) * G4], ibase[(size_t)(2 * q + 1) * G4]);
    }
    const float bin = b_in[gcol];

    // peer SMEM addresses
    uint32_t my_h = smem_u32(sh_h), my_xh = smem_u32(sh_xh);
    uint32_t peer_h[CPG], peer_xh[CPG];
#pragma unroll
    for (int r = 0; r < CPG; r++) {
        peer_h[r]  = mapa_u32(my_h, r);
        peer_xh[r] = mapa_u32(my_xh, r);
    }

    // elementwise role (t < 128): batch row bl, own hidden col
    const int bl = t >> 5, hc = t & 31;
    const int h_own = cs * 32 + hc;
    const uint32_t offb_x  = (uint32_t)(bl * 272 + (h_own >> 6) * 68 + (h_own & 63)) * 4u;
    const uint32_t offb_x2 = offb_x + 2u * 68u * 4u;
    const uint32_t offb_h  = (uint32_t)(bl * 136 + (h_own >> 6) * 68 + (h_own & 63)) * 4u;
    float c_reg = 0.f, cn_reg = 0.f, o_reg = 0.f;

    for (int q = t; q < BG * 2 * 68; q += 256) sh_h[q] = 0.f;  // h0 = 0
    __syncthreads();
    CLUSTER_SYNC_();

    const float* xp_base = g_Xp + (size_t)(g * BG) * G4 + gcol + (size_t)(kp * 2) * G4;

    for (int s = 0; s < S_LEN; s++) {
        // prefetch Xp rows (kp0: r0,r1; kp1: r2,r3)
        const float* xp = xp_base + (size_t)s * BATCH * G4;
        float xpa = __ldcs(xp), xpb = __ldcs(xp + G4);

        // ---- outer GEMM: K-half kp, 4 rows, k-parity-packed accumulators ----
        unsigned long long a0 = 0ull, a1 = 0ull, a2 = 0ull, a3 = 0ull;
        {
            const ulonglong2* h0 = (const ulonglong2*)(sh_h + 0 * 136 + kp * 68);
            const ulonglong2* h1 = (const ulonglong2*)(sh_h + 1 * 136 + kp * 68);
            const ulonglong2* h2 = (const ulonglong2*)(sh_h + 2 * 136 + kp * 68);
            const ulonglong2* h3 = (const ulonglong2*)(sh_h + 3 * 136 + kp * 68);
#pragma unroll
            for (int q2 = 0; q2 < 16; q2++) {
                ulonglong2 x0 = h0[q2], x1 = h1[q2], x2 = h2[q2], x3 = h3[q2];
                unsigned long long wA = wo[2 * q2], wB = wo[2 * q2 + 1];
                ffma2(a0, x0.x, wA); ffma2(a0, x0.y, wB);
                ffma2(a1, x1.x, wA); ffma2(a1, x1.y, wB);
                ffma2(a2, x2.x, wA); ffma2(a2, x2.y, wB);
                ffma2(a3, x3.x, wA); ffma2(a3, x3.y, wB);
            }
        }
        {
            float s0 = sum2(a0), s1 = sum2(a1), s2 = sum2(a2), s3 = sum2(a3);
            s0 += __shfl_xor_sync(0xffffffffu, s0, 1);
            s1 += __shfl_xor_sync(0xffffffffu, s1, 1);
            s2 += __shfl_xor_sync(0xffffffffu, s2, 1);
            s3 += __shfl_xor_sync(0xffffffffu, s3, 1);
            if (kp == 0) { sg[0 * 128 + j] = s0 + xpa; sg[1 * 128 + j] = s1 + xpb; }
            else         { sg[2 * 128 + j] = s2 + xpa; sg[3 * 128 + j] = s3 + xpb; }
        }
        __syncthreads();

        // ---- elementwise 1: push x_in, h_in into all peers' sh_xh ----
        if (t < 128) {
            float i_ = sigf(sg[bl * 128 + hc]);
            float f_ = sigf(sg[bl * 128 + 32 + hc]);
            o_reg    = sigf(sg[bl * 128 + 64 + hc]);
            float g_ = tanhf(sg[bl * 128 + 96 + hc]);
            float xin = i_ * g_;
            float hin = f_ * c_reg;
#pragma unroll
            for (int r = 0; r < CPG; r++) {
                st_cluster_f32(peer_xh[r] + offb_x,  xin);
                st_cluster_f32(peer_xh[r] + offb_x2, hin);
            }
        }
        CLUSTER_SYNC_();

        // ---- inner GEMM: K-half kp of K=256 (two 64-chunks) ----
        a0 = a1 = a2 = a3 = 0ull;
        {
            const ulonglong2* h0 = (const ulonglong2*)(sh_xh + 0 * 272 + 2 * kp * 68);
            const ulonglong2* h1 = (const ulonglong2*)(sh_xh + 1 * 272 + 2 * kp * 68);
            const ulonglong2* h2 = (const ulonglong2*)(sh_xh + 2 * 272 + 2 * kp * 68);
            const ulonglong2* h3 = (const ulonglong2*)(sh_xh + 3 * 272 + 2 * kp * 68);
#pragma unroll
            for (int q2 = 0; q2 < 16; q2++) {
                ulonglong2 x0 = h0[q2], x1 = h1[q2], x2 = h2[q2], x3 = h3[q2];
                unsigned long long wA = wi[2 * q2], wB = wi[2 * q2 + 1];
                ffma2(a0, x0.x, wA); ffma2(a0, x0.y, wB);
                ffma2(a1, x1.x, wA); ffma2(a1, x1.y, wB);
                ffma2(a2, x2.x, wA); ffma2(a2, x2.y, wB);
                ffma2(a3, x3.x, wA); ffma2(a3, x3.y, wB);
            }
#pragma unroll
            for (int q2 = 0; q2 < 16; q2++) {
                ulonglong2 x0 = h0[17 + q2], x1 = h1[17 + q2], x2 = h2[17 + q2], x3 = h3[17 + q2];
                unsigned long long wA = wi[32 + 2 * q2], wB = wi[33 + 2 * q2];
                ffma2(a0, x0.x, wA); ffma2(a0, x0.y, wB);
                ffma2(a1, x1.x, wA); ffma2(a1, x1.y, wB);
                ffma2(a2, x2.x, wA); ffma2(a2, x2.y, wB);
                ffma2(a3, x3.x, wA); ffma2(a3, x3.y, wB);
            }
        }
        {
            float s0 = sum2(a0), s1 = sum2(a1), s2 = sum2(a2), s3 = sum2(a3);
            s0 += __shfl_xor_sync(0xffffffffu, s0, 1);
            s1 += __shfl_xor_sync(0xffffffffu, s1, 1);
            s2 += __shfl_xor_sync(0xffffffffu, s2, 1);
            s3 += __shfl_xor_sync(0xffffffffu, s3, 1);
            if (kp == 0) { sg[0 * 128 + j] = s0 + bin; sg[1 * 128 + j] = s1 + bin; }
            else         { sg[2 * 128 + j] = s2 + bin; sg[3 * 128 + j] = s3 + bin; }
        }
        __syncthreads();

        // ---- elementwise 2: update state; push h into all peers' sh_h ----
        if (t < 128) {
            float ii = sigf(sg[bl * 128 + hc]);
            float fi = sigf(sg[bl * 128 + 32 + hc]);
            float oi = sigf(sg[bl * 128 + 64 + hc]);
            float gg = tanhf(sg[bl * 128 + 96 + hc]);
            cn_reg = fi * cn_reg + ii * gg;
            c_reg  = oi * tanhf(cn_reg);
            float hnew = o_reg * tanhf(c_reg);
#pragma unroll
            for (int r = 0; r < CPG; r++) st_cluster_f32(peer_h[r] + offb_h, hnew);
            g_hs[((size_t)s * HID + h_own) * BATCH + g * BG + bl] = hnew;
        }
        CLUSTER_SYNC_();
    }
}

// ---- Kernel 3: out[b][s][o] = b_lin[o] + sum_h hs[s][h][b] * W_lin[o][h] ----
__global__ __launch_bounds__(256) void out_kernel(const float* __restrict__ Wl,
                                                  const float* __restrict__ bl,
                                                  float* __restrict__ out) {
    extern __shared__ float sm[];
    float* hsb = sm;
    float* wls = sm + 16384;

    const int s = blockIdx.x;
    const int t = threadIdx.x;
    const int o = t & 63;
    const int b0 = (t >> 6) * 32;

    const float4* src = (const float4*)(g_hs + (size_t)s * HID * BATCH);
    for (int q = t; q < 4096; q += 256) ((float4*)hsb)[q] = src[q];
    for (int q = t; q < 8192; q += 256) {
        int oo = q >> 7, k = q & 127;
        wls[k * 65 + oo] = Wl[q];
    }
    __syncthreads();

    float acc[32];
#pragma unroll
    for (int jj = 0; jj < 32; jj++) acc[jj] = 0.f;
#pragma unroll 2
    for (int k = 0; k < HID; k++) {
        float wv = wls[k * 65 + o];
        const float4* hr = (const float4*)(hsb + k * 128 + b0);
#pragma unroll
        for (int j4 = 0; j4 < 8; j4++) {
            float4 hv = hr[j4];
            acc[4 * j4 + 0] = fmaf(hv.x, wv, acc[4 * j4 + 0]);
            acc[4 * j4 + 1] = fmaf(hv.y, wv, acc[4 * j4 + 1]);
            acc[4 * j4 + 2] = fmaf(hv.z, wv, acc[4 * j4 + 2]);
            acc[4 * j4 + 3] = fmaf(hv.w, wv, acc[4 * j4 + 3]);
        }
    }
    float bb = bl[o];
#pragma unroll
    for (int jj = 0; jj < 32; jj++) {
        out[((size_t)(b0 + jj) * S_LEN + s) * OUT_DIM + o] = acc[jj] + bb;
    }
}

extern "C" void kernel_launch(void* const* d_in, const int* in_sizes, int n_in,
                              void* d_out, int out_size) {
    const float* x      = (const float*)d_in[0];
    const float* Wx_out = (const float*)d_in[1];
    const float* Wh_out = (const float*)d_in[2];
    const float* b_out  = (const float*)d_in[3];
    const float* Wx_in  = (const float*)d_in[4];
    const float* Wh_in  = (const float*)d_in[5];
    const float* b_in   = (const float*)d_in[6];
    const float* W_lin  = (const float*)d_in[7];
    const float* b_lin  = (const float*)d_in[8];
    float* out = (float*)d_out;

    cudaFuncSetAttribute(out_kernel, cudaFuncAttributeMaxDynamicSharedMemorySize, OUT_SMEM);

    xproj_kernel<<<dim3(S_LEN, BATCH / 32), 256>>>(x, Wx_out, b_out);
    rec_kernel<<<NCTA, 256>>>(Wh_out, Wx_in, Wh_in, b_in);
    out_kernel<<<S_LEN, 256, OUT_SMEM>>>(W_lin, b_lin, out);
}

// round 7
// speedup vs baseline: 3.2361x; 1.3745x over previous
#include <cuda_runtime.h>
#include <cstdint>

#define S_LEN 2048
#define BATCH 128
#define IN_DIM 64
#define HID 128
#define G4 512
#define OUT_DIM 64
#define NGROUP 32
#define CPG 4
#define BG 4
#define NCTA (NGROUP * CPG)

// ---- static device scratch ----
__device__ float g_Xp[(size_t)S_LEN * BATCH * G4];   // [s][b][n]
__device__ float g_hs[(size_t)S_LEN * BATCH * HID];  // [s][b][h]  (coalesced rec stores)

#define OUT_SMEM ((128 * 136 + 128 * 65) * 4)

__device__ __forceinline__ float sigf(float v) {
    return __fdividef(1.f, 1.f + __expf(-v));
}
__device__ __forceinline__ float tanhf_fast(float x) {
    float cx = fminf(fmaxf(x, -15.f), 15.f);
    float e = __expf(2.f * cx);
    return __fdividef(e - 1.f, e + 1.f);
}

__device__ __forceinline__ uint32_t smem_u32(const void* p) {
    uint32_t a;
    asm("{ .reg .u64 t; cvta.to.shared.u64 t, %1; cvt.u32.u64 %0, t; }" : "=r"(a) : "l"(p));
    return a;
}
__device__ __forceinline__ uint32_t mapa_u32(uint32_t local_addr, int rank) {
    uint32_t r;
    asm("mapa.shared::cluster.u32 %0, %1, %2;" : "=r"(r) : "r"(local_addr), "r"(rank));
    return r;
}
#define CLUSTER_SYNC_() do { \
    asm volatile("barrier.cluster.arrive.aligned;" ::: "memory"); \
    asm volatile("barrier.cluster.wait.aligned;" ::: "memory"); \
} while (0)

#define MBAR_INIT(addr, cnt) \
    asm volatile("mbarrier.init.shared.b64 [%0], %1;" :: "r"(addr), "r"(cnt) : "memory")
#define MBAR_ARM(addr, bytes) \
    asm volatile("mbarrier.arrive.expect_tx.shared.b64 _, [%0], %1;" :: "r"(addr), "r"(bytes) : "memory")
#define MBAR_WAIT(addr, parity) do { \
    asm volatile("{\n\t.reg .pred P1;\n\t" \
        "WAIT_%=:\n\t" \
        "mbarrier.try_wait.parity.acquire.cta.shared::cta.b64 P1, [%0], %1, 0x989680;\n\t" \
        "@P1 bra.uni DONE_%=;\n\t" \
        "bra.uni WAIT_%=;\n\t" \
        "DONE_%=:\n\t}" \
        :: "r"(addr), "r"(parity) : "memory"); \
} while (0)

__device__ __forceinline__ void st_async_f32(uint32_t daddr, uint32_t dmbar, float v) {
    asm volatile("st.async.shared::cluster.mbarrier::complete_tx::bytes.f32 [%0], %1, [%2];"
                 :: "r"(daddr), "f"(v), "r"(dmbar) : "memory");
}
__device__ __forceinline__ void st_async_v2f32(uint32_t daddr, uint32_t dmbar, float a, float b) {
    asm volatile("st.async.shared::cluster.mbarrier::complete_tx::bytes.v2.f32 [%0], {%1, %2}, [%3];"
                 :: "r"(daddr), "f"(a), "f"(b), "r"(dmbar) : "memory");
}

__device__ __forceinline__ void ffma2(unsigned long long& d, unsigned long long a, unsigned long long b) {
    asm("fma.rn.f32x2 %0, %1, %2, %0;" : "+l"(d) : "l"(a), "l"(b));
}
__device__ __forceinline__ unsigned long long pack2(float a, float b) {
    unsigned long long p;
    asm("mov.b64 %0, {%1, %2};" : "=l"(p) : "f"(a), "f"(b));
    return p;
}
__device__ __forceinline__ float sum2(unsigned long long p) {
    float lo, hi;
    asm("mov.b64 {%0, %1}, %2;" : "=f"(lo), "=f"(hi) : "l"(p));
    return lo + hi;
}

// ---- Kernel 1: Xp[s][b][n] = b_out[n] + sum_i x[b][i][s] * Wx_out[i][n] ----
__global__ __launch_bounds__(256) void xproj_kernel(const float* __restrict__ x,
                                                    const float* __restrict__ Wx,
                                                    const float* __restrict__ bo) {
    __shared__ float xs[IN_DIM * 33];
    const int s = blockIdx.x;
    const int b0 = blockIdx.y * 32;
    const int t = threadIdx.x;
    const int b = t & 31;
    const int n0 = (t >> 5) * 64;

    for (int q = t; q < 32 * IN_DIM; q += 256) {
        int bb = q >> 6, i = q & 63;
        xs[i * 33 + bb] = x[((size_t)(b0 + bb) * IN_DIM + i) * S_LEN + s];
    }
    __syncthreads();

    float acc[64];
#pragma unroll
    for (int j = 0; j < 64; j++) acc[j] = 0.f;
#pragma unroll 2
    for (int k = 0; k < IN_DIM; k++) {
        float xv = xs[k * 33 + b];
        const float4* wr = (const float4*)(Wx + (size_t)k * G4 + n0);
#pragma unroll
        for (int j4 = 0; j4 < 16; j4++) {
            float4 w = __ldg(&wr[j4]);
            acc[4 * j4 + 0] = fmaf(xv, w.x, acc[4 * j4 + 0]);
            acc[4 * j4 + 1] = fmaf(xv, w.y, acc[4 * j4 + 1]);
            acc[4 * j4 + 2] = fmaf(xv, w.z, acc[4 * j4 + 2]);
            acc[4 * j4 + 3] = fmaf(xv, w.w, acc[4 * j4 + 3]);
        }
    }
#pragma unroll
    for (int j = 0; j < 64; j++) {
        g_Xp[((size_t)s * BATCH + b0 + b) * G4 + n0 + j] = acc[j] + __ldg(&bo[n0 + j]);
    }
}

// ---- Kernel 2: persistent recurrence; cluster of 4 CTAs = 1 group (4 batch rows).
//      Register-resident weights, FFMA2, st.async + mbarrier exchange. ----
__global__ __launch_bounds__(256, 1) __cluster_dims__(CPG, 1, 1)
void rec_kernel(const float* __restrict__ Wh_out,
                const float* __restrict__ Wx_in,
                const float* __restrict__ Wh_in,
                const float* __restrict__ b_in) {
    // exchange buffers: [r][chunk][68] (68-float chunks: 64 data + 4 pad)
    __shared__ __align__(16) float sh_h[BG * 2 * 68];     // k < 128 (h)
    __shared__ __align__(16) float sh_xh[BG * 4 * 68];    // k' < 256, k'=2h -> x_in, 2h+1 -> h_in
    __shared__ float sg[BG * 128];                        // gates [r][j]
    __shared__ __align__(8) unsigned long long mbars[2];  // [0]=xh, [1]=h
    __shared__ uint32_t ptab[CPG * 4];                    // per rank: xh_addr, h_addr, xh_bar, h_bar

    const int cta = blockIdx.x;
    const int g   = cta >> 2;
    const int t   = threadIdx.x;
    const int j   = t >> 1;            // gate column 0..127
    const int kp  = t & 1;             // K-half
    uint32_t cs;
    asm("mov.u32 %0, %%cluster_ctarank;" : "=r"(cs));
    const int gcol = (j >> 5) * 128 + (int)cs * 32 + (j & 31);

    // ---- register-resident weights ----
    unsigned long long wo[32];   // outer: k = kp*64 + 2q -> {Wh_out[k], Wh_out[k+1]}
    unsigned long long wi[64];   // inner: k' = kp*128 + 2q -> {Wx_in[h], Wh_in[h]}, h = kp*64 + q
    {
        const float* wbase = Wh_out + (size_t)(kp * 64) * G4 + gcol;
#pragma unroll
        for (int q = 0; q < 32; q++)
            wo[q] = pack2(wbase[(size_t)(2 * q) * G4], wbase[(size_t)(2 * q + 1) * G4]);
        const int hh0 = kp * 64;
#pragma unroll
        for (int q = 0; q < 64; q++)
            wi[q] = pack2(Wx_in[(size_t)(hh0 + q) * G4 + gcol],
                          Wh_in[(size_t)(hh0 + q) * G4 + gcol]);
    }
    const float bin = b_in[gcol];

    // peer address table + mbarrier init/arm
    if (t < CPG) {
        uint32_t xh0 = smem_u32(sh_xh), h0a = smem_u32(sh_h);
        uint32_t bx = smem_u32(&mbars[0]), bh = smem_u32(&mbars[1]);
        ptab[t * 4 + 0] = mapa_u32(xh0, t);
        ptab[t * 4 + 1] = mapa_u32(h0a, t);
        ptab[t * 4 + 2] = mapa_u32(bx, t);
        ptab[t * 4 + 3] = mapa_u32(bh, t);
    }
    const uint32_t bx_loc = smem_u32(&mbars[0]);
    const uint32_t bh_loc = smem_u32(&mbars[1]);
    if (t == 0) {
        MBAR_INIT(bx_loc, 1);
        MBAR_INIT(bh_loc, 1);
        MBAR_ARM(bx_loc, 4096u);   // phase 0
        MBAR_ARM(bh_loc, 2048u);   // phase 0
    }
    for (int q = t; q < BG * 2 * 68; q += 256) sh_h[q] = 0.f;  // h0 = 0
    __syncthreads();
    CLUSTER_SYNC_();   // all peers' mbars initialized+armed before any st.async

    // owner role (t < 128): batch row bl, own hidden col
    const int bl = t >> 5, hc = t & 31;
    const int h_own = (int)cs * 32 + hc;
    const int kxi = 2 * h_own;  // interleaved k' for (x_in, h_in) pair
    const uint32_t offb_x = (uint32_t)(bl * 272 + (kxi >> 6) * 68 + (kxi & 63)) * 4u;
    const uint32_t offb_h = (uint32_t)(bl * 136 + (h_own >> 6) * 68 + (h_own & 63)) * 4u;
    float c_reg = 0.f, cn_reg = 0.f, o_reg = 0.f;

    const float* xp_base = g_Xp + (size_t)(g * BG) * G4 + gcol + (size_t)(kp * 2) * G4;

    for (int s = 0; s < S_LEN; s++) {
        const uint32_t par = (uint32_t)(s & 1);
        // prefetch Xp rows (kp0: r0,r1; kp1: r2,r3)
        const float* xp = xp_base + (size_t)s * BATCH * G4;
        float xpa = __ldcs(xp), xpb = __ldcs(xp + G4);

        // ---- outer GEMM: K-half kp, 4 rows ----
        unsigned long long a0 = 0ull, a1 = 0ull, a2 = 0ull, a3 = 0ull;
        {
            const ulonglong2* h0 = (const ulonglong2*)(sh_h + 0 * 136 + kp * 68);
            const ulonglong2* h1 = (const ulonglong2*)(sh_h + 1 * 136 + kp * 68);
            const ulonglong2* h2 = (const ulonglong2*)(sh_h + 2 * 136 + kp * 68);
            const ulonglong2* h3 = (const ulonglong2*)(sh_h + 3 * 136 + kp * 68);
#pragma unroll
            for (int q2 = 0; q2 < 16; q2++) {
                ulonglong2 x0 = h0[q2], x1 = h1[q2], x2 = h2[q2], x3 = h3[q2];
                unsigned long long wA = wo[2 * q2], wB = wo[2 * q2 + 1];
                ffma2(a0, x0.x, wA); ffma2(a0, x0.y, wB);
                ffma2(a1, x1.x, wA); ffma2(a1, x1.y, wB);
                ffma2(a2, x2.x, wA); ffma2(a2, x2.y, wB);
                ffma2(a3, x3.x, wA); ffma2(a3, x3.y, wB);
            }
        }
        {
            float s0 = sum2(a0), s1 = sum2(a1), s2 = sum2(a2), s3 = sum2(a3);
            s0 += __shfl_xor_sync(0xffffffffu, s0, 1);
            s1 += __shfl_xor_sync(0xffffffffu, s1, 1);
            s2 += __shfl_xor_sync(0xffffffffu, s2, 1);
            s3 += __shfl_xor_sync(0xffffffffu, s3, 1);
            if (kp == 0) { sg[0 * 128 + j] = s0 + xpa; sg[1 * 128 + j] = s1 + xpb; }
            else         { sg[2 * 128 + j] = s2 + xpa; sg[3 * 128 + j] = s3 + xpb; }
        }
        __syncthreads();

        // ---- elementwise 1: push interleaved (x_in, h_in) to all ranks ----
        if (t < 128) {
            float i_ = sigf(sg[bl * 128 + hc]);
            float f_ = sigf(sg[bl * 128 + 32 + hc]);
            o_reg    = sigf(sg[bl * 128 + 64 + hc]);
            float g_ = tanhf_fast(sg[bl * 128 + 96 + hc]);
            float xin = i_ * g_;
            float hin = f_ * c_reg;
#pragma unroll
            for (int r = 0; r < CPG; r++)
                st_async_v2f32(ptab[r * 4 + 0] + offb_x, ptab[r * 4 + 2], xin, hin);
        }
        MBAR_WAIT(bx_loc, par);
        if (t == 0) MBAR_ARM(bx_loc, 4096u);

        // ---- inner GEMM: K'=256 interleaved, half per kp ----
        a0 = a1 = a2 = a3 = 0ull;
        {
            const ulonglong2* h0 = (const ulonglong2*)(sh_xh + 0 * 272 + 2 * kp * 68);
            const ulonglong2* h1 = (const ulonglong2*)(sh_xh + 1 * 272 + 2 * kp * 68);
            const ulonglong2* h2 = (const ulonglong2*)(sh_xh + 2 * 272 + 2 * kp * 68);
            const ulonglong2* h3 = (const ulonglong2*)(sh_xh + 3 * 272 + 2 * kp * 68);
#pragma unroll
            for (int q2 = 0; q2 < 16; q2++) {
                ulonglong2 x0 = h0[q2], x1 = h1[q2], x2 = h2[q2], x3 = h3[q2];
                unsigned long long wA = wi[2 * q2], wB = wi[2 * q2 + 1];
                ffma2(a0, x0.x, wA); ffma2(a0, x0.y, wB);
                ffma2(a1, x1.x, wA); ffma2(a1, x1.y, wB);
                ffma2(a2, x2.x, wA); ffma2(a2, x2.y, wB);
                ffma2(a3, x3.x, wA); ffma2(a3, x3.y, wB);
            }
#pragma unroll
            for (int q2 = 0; q2 < 16; q2++) {
                ulonglong2 x0 = h0[17 + q2], x1 = h1[17 + q2], x2 = h2[17 + q2], x3 = h3[17 + q2];
                unsigned long long wA = wi[32 + 2 * q2], wB = wi[33 + 2 * q2];
                ffma2(a0, x0.x, wA); ffma2(a0, x0.y, wB);
                ffma2(a1, x1.x, wA); ffma2(a1, x1.y, wB);
                ffma2(a2, x2.x, wA); ffma2(a2, x2.y, wB);
                ffma2(a3, x3.x, wA); ffma2(a3, x3.y, wB);
            }
        }
        {
            float s0 = sum2(a0), s1 = sum2(a1), s2 = sum2(a2), s3 = sum2(a3);
            s0 += __shfl_xor_sync(0xffffffffu, s0, 1);
            s1 += __shfl_xor_sync(0xffffffffu, s1, 1);
            s2 += __shfl_xor_sync(0xffffffffu, s2, 1);
            s3 += __shfl_xor_sync(0xffffffffu, s3, 1);
            if (kp == 0) { sg[0 * 128 + j] = s0 + bin; sg[1 * 128 + j] = s1 + bin; }
            else         { sg[2 * 128 + j] = s2 + bin; sg[3 * 128 + j] = s3 + bin; }
        }
        __syncthreads();

        // ---- elementwise 2: update state; push h to all ranks ----
        if (t < 128) {
            float ii = sigf(sg[bl * 128 + hc]);
            float fi = sigf(sg[bl * 128 + 32 + hc]);
            float oi = sigf(sg[bl * 128 + 64 + hc]);
            float gg = tanhf_fast(sg[bl * 128 + 96 + hc]);
            cn_reg = fi * cn_reg + ii * gg;
            c_reg  = oi * tanhf_fast(cn_reg);
            float hnew = o_reg * tanhf_fast(c_reg);
#pragma unroll
            for (int r = 0; r < CPG; r++)
                st_async_f32(ptab[r * 4 + 1] + offb_h, ptab[r * 4 + 3], hnew);
            g_hs[((size_t)s * BATCH + g * BG + bl) * HID + h_own] = hnew;
        }
        MBAR_WAIT(bh_loc, par);
        if (t == 0) MBAR_ARM(bh_loc, 2048u);
    }
    CLUSTER_SYNC_();
}

// ---- Kernel 3: out[b][s][o] = b_lin[o] + sum_h hs[s][b][h] * W_lin[o][h] ----
__global__ __launch_bounds__(256) void out_kernel(const float* __restrict__ Wl,
                                                  const float* __restrict__ bl,
                                                  float* __restrict__ out) {
    extern __shared__ float sm[];
    float* hsb = sm;               // transposed [h][b], pad 136
    float* wls = sm + 128 * 136;   // [h][o] pad 65

    const int s = blockIdx.x;
    const int t = threadIdx.x;
    const int o = t & 63;
    const int b0 = (t >> 6) * 32;

    const float* src = g_hs + (size_t)s * BATCH * HID;   // [b][h]
    for (int q = t; q < 16384; q += 256) {
        int b = q >> 7, h = q & 127;
        hsb[h * 136 + b] = src[q];
    }
    for (int q = t; q < 8192; q += 256) {
        int oo = q >> 7, k = q & 127;
        wls[k * 65 + oo] = Wl[q];
    }
    __syncthreads();

    float acc[32];
#pragma unroll
    for (int jj = 0; jj < 32; jj++) acc[jj] = 0.f;
#pragma unroll 2
    for (int k = 0; k < HID; k++) {
        float wv = wls[k * 65 + o];
        const float4* hr = (const float4*)(hsb + k * 136 + b0);
#pragma unroll
        for (int j4 = 0; j4 < 8; j4++) {
            float4 hv = hr[j4];
            acc[4 * j4 + 0] = fmaf(hv.x, wv, acc[4 * j4 + 0]);
            acc[4 * j4 + 1] = fmaf(hv.y, wv, acc[4 * j4 + 1]);
            acc[4 * j4 + 2] = fmaf(hv.z, wv, acc[4 * j4 + 2]);
            acc[4 * j4 + 3] = fmaf(hv.w, wv, acc[4 * j4 + 3]);
        }
    }
    float bb = bl[o];
#pragma unroll
    for (int jj = 0; jj < 32; jj++) {
        out[((size_t)(b0 + jj) * S_LEN + s) * OUT_DIM + o] = acc[jj] + bb;
    }
}

extern "C" void kernel_launch(void* const* d_in, const int* in_sizes, int n_in,
                              void* d_out, int out_size) {
    const float* x      = (const float*)d_in[0];
    const float* Wx_out = (const float*)d_in[1];
    const float* Wh_out = (const float*)d_in[2];
    const float* b_out  = (const float*)d_in[3];
    const float* Wx_in  = (const float*)d_in[4];
    const float* Wh_in  = (const float*)d_in[5];
    const float* b_in   = (const float*)d_in[6];
    const float* W_lin  = (const float*)d_in[7];
    const float* b_lin  = (const float*)d_in[8];
    float* out = (float*)d_out;

    cudaFuncSetAttribute(out_kernel, cudaFuncAttributeMaxDynamicSharedMemorySize, OUT_SMEM);

    xproj_kernel<<<dim3(S_LEN, BATCH / 32), 256>>>(x, Wx_out, b_out);
    rec_kernel<<<NCTA, 256>>>(Wh_out, Wx_in, Wh_in, b_in);
    out_kernel<<<S_LEN, 256, OUT_SMEM>>>(W_lin, b_lin, out);
}